// round 1
// baseline (speedup 1.0000x reference)
#include <cuda_runtime.h>
#include <math.h>

#define NN 50000            // nodes
#define NE 800000           // edges
#define NG 512              // graphs
#define DD 128              // node hidden
#define MM 256              // message hidden
#define TT 4                // edge types
#define NPASS 4
#define GH 256              // graph hidden

// ---------------- scratch (static __device__, no allocations) ----------------
__device__ float g_h[NN * DD];                // node hidden state
__device__ float g_preagg[NN * (TT * DD)];    // (N, 512) node-major [t0|t1|t2|t3]
__device__ int   g_counts[NN * TT];
__device__ float g_msgs[NN * MM];
__device__ float g_gi[NN * 3 * DD];
__device__ float g_gh[NN * 3 * DD];
__device__ float g_attn[NN];
__device__ int   g_hist[NN];
__device__ int   g_cursor[NN];
__device__ int   g_off[NN + 1];
__device__ int2  g_csr[NE];                   // (dst, type) sorted by src

// ---------------- setup kernels ----------------
__global__ void k_zero2(int* a, int* b, int n) {
    int i = blockIdx.x * blockDim.x + threadIdx.x;
    if (i < n) { a[i] = 0; b[i] = 0; }
}

__global__ void k_hist(const int* __restrict__ src, int* __restrict__ hist) {
    int i = blockIdx.x * blockDim.x + threadIdx.x;
    if (i < NE) atomicAdd(&hist[src[i]], 1);
}

// single-block chunked exclusive scan of g_hist -> g_off
__global__ void k_scan(const int* __restrict__ hist, int* __restrict__ off) {
    __shared__ int sh[1024];
    __shared__ int s_run;
    int tid = threadIdx.x;
    if (tid == 0) s_run = 0;
    __syncthreads();
    for (int base = 0; base < NN; base += 1024) {
        int i = base + tid;
        int v = (i < NN) ? hist[i] : 0;
        sh[tid] = v;
        __syncthreads();
        for (int o = 1; o < 1024; o <<= 1) {
            int t = (tid >= o) ? sh[tid - o] : 0;
            __syncthreads();
            sh[tid] += t;
            __syncthreads();
        }
        int run = s_run;
        if (i < NN) off[i] = run + sh[tid] - v;
        __syncthreads();
        if (tid == 1023) s_run = run + sh[1023];
        __syncthreads();
    }
    if (tid == 0) off[NN] = NE;
}

__global__ void k_scatter(const int* __restrict__ src, const int* __restrict__ dst,
                          const int* __restrict__ typ,
                          const int* __restrict__ off, int* __restrict__ cursor,
                          int2* __restrict__ csr) {
    int i = blockIdx.x * blockDim.x + threadIdx.x;
    if (i >= NE) return;
    int s = src[i];
    int pos = off[s] + atomicAdd(&cursor[s], 1);
    csr[pos] = make_int2(dst[i], typ[i]);
}

__global__ void k_embed(const int* __restrict__ nt, const float* __restrict__ emb,
                        float* __restrict__ h) {
    int t = blockIdx.x * blockDim.x + threadIdx.x;
    if (t >= NN * 32) return;
    int node = t >> 5, c = t & 31;
    reinterpret_cast<float4*>(h)[t] =
        reinterpret_cast<const float4*>(emb)[nt[node] * 32 + c];
}

// ---------------- per-pass: CSR aggregation (warp per node) ----------------
__global__ void k_agg(const float* __restrict__ h, const int* __restrict__ off,
                      const int2* __restrict__ csr,
                      float* __restrict__ preagg, int* __restrict__ counts) {
    int warp = (blockIdx.x * blockDim.x + threadIdx.x) >> 5;
    int lane = threadIdx.x & 31;
    if (warp >= NN) return;
    int beg = off[warp], end = off[warp + 1];
    float4 a0 = make_float4(0, 0, 0, 0), a1 = a0, a2 = a0, a3 = a0;
    int c0 = 0, c1 = 0, c2 = 0, c3 = 0;
    const float4* h4 = reinterpret_cast<const float4*>(h);
    for (int e = beg; e < end; ++e) {
        int2 dt = csr[e];
        float4 v = h4[dt.x * 32 + lane];
        switch (dt.y) {
            case 0: a0.x += v.x; a0.y += v.y; a0.z += v.z; a0.w += v.w; c0++; break;
            case 1: a1.x += v.x; a1.y += v.y; a1.z += v.z; a1.w += v.w; c1++; break;
            case 2: a2.x += v.x; a2.y += v.y; a2.z += v.z; a2.w += v.w; c2++; break;
            default:a3.x += v.x; a3.y += v.y; a3.z += v.z; a3.w += v.w; c3++; break;
        }
    }
    float4* p4 = reinterpret_cast<float4*>(preagg);
    int base = warp * 128;  // 512 floats = 128 float4 per node
    p4[base +       lane] = a0;
    p4[base +  32 + lane] = a1;
    p4[base +  64 + lane] = a2;
    p4[base +  96 + lane] = a3;
    if (lane == 0) {
        counts[warp * 4 + 0] = c0; counts[warp * 4 + 1] = c1;
        counts[warp * 4 + 2] = c2; counts[warp * 4 + 3] = c3;
    }
}

// ---------------- SGEMM 128x128x8, 8x8 microtile, fused epilogues ----------------
// MODE 0: C = acc + bias[col]
// MODE 1: C = relu(acc + sum_t counts[r][t]*bmsg[t*MM+col])
// MODE 2: atomicAdd(gout[n2g[r]*GH+col], attn[r]*(acc+bias[col]))
template <int MODE, bool TRANSB>
__global__ void __launch_bounds__(256)
k_sgemm(const float* __restrict__ A, const float* __restrict__ B,
        float* __restrict__ C, int Nrows, int K, int Ncols,
        const float* __restrict__ bias,
        const int* __restrict__ counts, const float* __restrict__ bmsg,
        const float* __restrict__ attn, const int* __restrict__ n2g,
        float* __restrict__ gout) {
    constexpr int BM = 128, BN = 128, BK = 8, TM = 8, TN = 8;
    __shared__ float As[BK][BM];
    __shared__ float Bs[BK][BN];
    const int tid = threadIdx.x;
    const int rowBase = blockIdx.x * BM;
    const int colBase = blockIdx.y * BN;
    const int tr = tid >> 4;           // 0..15
    const int tc = tid & 15;           // 0..15
    const int aRow = tid >> 1;         // 0..127
    const int aCol = (tid & 1) * 4;    // 0 or 4
    const int bRow = tid >> 5;         // 0..7
    const int bCol = (tid & 31) * 4;   // 0..124

    float acc[TM][TN];
#pragma unroll
    for (int i = 0; i < TM; i++)
#pragma unroll
        for (int j = 0; j < TN; j++) acc[i][j] = 0.f;

    for (int k0 = 0; k0 < K; k0 += BK) {
        float4 av = make_float4(0, 0, 0, 0);
        if (rowBase + aRow < Nrows)
            av = *reinterpret_cast<const float4*>(A + (size_t)(rowBase + aRow) * K + k0 + aCol);
        As[aCol + 0][aRow] = av.x; As[aCol + 1][aRow] = av.y;
        As[aCol + 2][aRow] = av.z; As[aCol + 3][aRow] = av.w;
        if (!TRANSB) {
            float4 bv = *reinterpret_cast<const float4*>(
                B + (size_t)(k0 + bRow) * Ncols + colBase + bCol);
            Bs[bRow][bCol + 0] = bv.x; Bs[bRow][bCol + 1] = bv.y;
            Bs[bRow][bCol + 2] = bv.z; Bs[bRow][bCol + 3] = bv.w;
        } else {
            // B is (Ncols x K) row-major: B[k][n] = Bm[n*K + k]
#pragma unroll
            for (int q = 0; q < 4; q++)
                Bs[bRow][bCol + q] = B[(size_t)(colBase + bCol + q) * K + k0 + bRow];
        }
        __syncthreads();
#pragma unroll
        for (int kk = 0; kk < BK; kk++) {
            float ar[TM], br[TN];
#pragma unroll
            for (int i = 0; i < TM; i++) ar[i] = As[kk][tr * TM + i];
#pragma unroll
            for (int j = 0; j < TN; j++) br[j] = Bs[kk][tc * TN + j];
#pragma unroll
            for (int i = 0; i < TM; i++)
#pragma unroll
                for (int j = 0; j < TN; j++) acc[i][j] += ar[i] * br[j];
        }
        __syncthreads();
    }

#pragma unroll
    for (int i = 0; i < TM; i++) {
        int r = rowBase + tr * TM + i;
        if (r >= Nrows) continue;
        if (MODE == 1) {
            float c0 = (float)counts[r * 4 + 0], c1 = (float)counts[r * 4 + 1];
            float c2 = (float)counts[r * 4 + 2], c3 = (float)counts[r * 4 + 3];
#pragma unroll
            for (int j = 0; j < TN; j++) {
                int c = colBase + tc * TN + j;
                float v = acc[i][j] + c0 * bmsg[c] + c1 * bmsg[MM + c] +
                          c2 * bmsg[2 * MM + c] + c3 * bmsg[3 * MM + c];
                C[(size_t)r * Ncols + c] = fmaxf(v, 0.f);
            }
        } else if (MODE == 0) {
#pragma unroll
            for (int j = 0; j < TN; j++) {
                int c = colBase + tc * TN + j;
                C[(size_t)r * Ncols + c] = acc[i][j] + bias[c];
            }
        } else {
            float a = attn[r];
            int g = n2g[r];
#pragma unroll
            for (int j = 0; j < TN; j++) {
                int c = colBase + tc * TN + j;
                atomicAdd(&gout[(size_t)g * GH + c], a * (acc[i][j] + bias[c]));
            }
        }
    }
}

// ---------------- GRU gates (elementwise) ----------------
__global__ void k_gates(const float* __restrict__ gi, const float* __restrict__ gh,
                        float* __restrict__ h) {
    int i = blockIdx.x * blockDim.x + threadIdx.x;
    if (i >= NN * DD) return;
    int n = i >> 7, j = i & 127;
    const float* gin = gi + (size_t)n * 3 * DD;
    const float* ghn = gh + (size_t)n * 3 * DD;
    float r = 1.f / (1.f + expf(-(gin[j] + ghn[j])));
    float z = 1.f / (1.f + expf(-(gin[DD + j] + ghn[DD + j])));
    float nn = tanhf(gin[2 * DD + j] + r * ghn[2 * DD + j]);
    h[i] = (1.f - z) * nn + z * h[i];
}

// ---------------- readout attn (warp per node) ----------------
__global__ void k_attn(const float* __restrict__ h, const float* __restrict__ wg,
                       const float* __restrict__ bg, float* __restrict__ attn) {
    int warp = (blockIdx.x * blockDim.x + threadIdx.x) >> 5;
    int lane = threadIdx.x & 31;
    if (warp >= NN) return;
    const float4* h4 = reinterpret_cast<const float4*>(h + (size_t)warp * DD);
    const float4* w4 = reinterpret_cast<const float4*>(wg);
    float4 a = h4[lane], b = w4[lane];
    float s = a.x * b.x + a.y * b.y + a.z * b.z + a.w * b.w;
#pragma unroll
    for (int o = 16; o; o >>= 1) s += __shfl_xor_sync(0xFFFFFFFFu, s, o);
    if (lane == 0) attn[warp] = 1.f / (1.f + expf(-(s + bg[0])));
}

// ---------------- launch ----------------
static inline void* symaddr(const void* sym) {
    void* p = nullptr;
    cudaGetSymbolAddress(&p, sym);
    return p;
}

extern "C" void kernel_launch(void* const* d_in, const int* in_sizes, int n_in,
                              void* d_out, int out_size) {
    const int*   node_types = (const int*)d_in[0];
    const int*   edge_src   = (const int*)d_in[1];
    const int*   edge_dst   = (const int*)d_in[2];
    const int*   edge_type  = (const int*)d_in[3];
    const int*   node2graph = (const int*)d_in[4];
    const float* emb   = (const float*)d_in[5];
    const float* W_msg = (const float*)d_in[6];   // (T,D,M) = (512,256) concat
    const float* b_msg = (const float*)d_in[7];   // (T,M)
    const float* W_ih  = (const float*)d_in[8];   // (384,256)
    const float* W_hh  = (const float*)d_in[9];   // (384,128)
    const float* b_ih  = (const float*)d_in[10];
    const float* b_hh  = (const float*)d_in[11];
    const float* w_gate= (const float*)d_in[12];  // (128)
    const float* b_gate= (const float*)d_in[13];  // (1)
    const float* W_g   = (const float*)d_in[14];  // (128,256)
    const float* b_g   = (const float*)d_in[15];  // (256)
    float* out = (float*)d_out;

    float* h      = (float*)symaddr(g_h);
    float* preagg = (float*)symaddr(g_preagg);
    int*   counts = (int*)  symaddr(g_counts);
    float* msgs   = (float*)symaddr(g_msgs);
    float* gi     = (float*)symaddr(g_gi);
    float* gh     = (float*)symaddr(g_gh);
    float* attn   = (float*)symaddr(g_attn);
    int*   hist   = (int*)  symaddr(g_hist);
    int*   cursor = (int*)  symaddr(g_cursor);
    int*   off    = (int*)  symaddr(g_off);
    int2*  csr    = (int2*) symaddr(g_csr);

    // --- build CSR by src (edges are launch-static, rebuilt deterministically-enough) ---
    k_zero2<<<(NN + 255) / 256, 256>>>(hist, cursor, NN);
    k_hist<<<(NE + 255) / 256, 256>>>(edge_src, hist);
    k_scan<<<1, 1024>>>(hist, off);
    k_scatter<<<(NE + 255) / 256, 256>>>(edge_src, edge_dst, edge_type, off, cursor, csr);

    // --- init h = emb_table[node_types] ---
    k_embed<<<(NN * 32 + 255) / 256, 256>>>(node_types, emb, h);

    const int rowBlocks = (NN + 127) / 128;  // 391

    for (int p = 0; p < NPASS; p++) {
        // pre_agg + counts
        k_agg<<<(NN * 32 + 255) / 256, 256>>>(h, off, csr, preagg, counts);
        // msgs = relu(pre_agg @ W_msg_cat + counts . b_msg)
        {
            dim3 g(rowBlocks, MM / 128);
            k_sgemm<1, false><<<g, 256>>>(preagg, W_msg, msgs, NN, TT * DD, MM,
                                          nullptr, counts, b_msg, nullptr, nullptr, nullptr);
        }
        // gi = msgs @ W_ih^T + b_ih
        {
            dim3 g(rowBlocks, (3 * DD) / 128);
            k_sgemm<0, true><<<g, 256>>>(msgs, W_ih, gi, NN, MM, 3 * DD,
                                         b_ih, nullptr, nullptr, nullptr, nullptr, nullptr);
        }
        // gh = h @ W_hh^T + b_hh
        {
            dim3 g(rowBlocks, (3 * DD) / 128);
            k_sgemm<0, true><<<g, 256>>>(h, W_hh, gh, NN, DD, 3 * DD,
                                         b_hh, nullptr, nullptr, nullptr, nullptr, nullptr);
        }
        // GRU gates -> h
        k_gates<<<(NN * DD + 255) / 256, 256>>>(gi, gh, h);
    }

    // --- output: h first, then gated graph readout ---
    size_t total = (size_t)NN * DD + (size_t)NG * GH;
    if ((size_t)out_size >= total)
        cudaMemcpyAsync(out, h, (size_t)NN * DD * sizeof(float),
                        cudaMemcpyDeviceToDevice);
    float* gout = out + ((size_t)out_size - (size_t)NG * GH);
    cudaMemsetAsync(gout, 0, (size_t)NG * GH * sizeof(float));

    k_attn<<<(NN * 32 + 255) / 256, 256>>>(h, w_gate, b_gate, attn);
    {
        dim3 g(rowBlocks, GH / 128);
        k_sgemm<2, false><<<g, 256>>>(h, W_g, nullptr, NN, DD, GH,
                                      b_g, nullptr, nullptr, attn, node2graph, gout);
    }
}

// round 2
// speedup vs baseline: 2.6512x; 2.6512x over previous
#include <cuda_runtime.h>
#include <math.h>

#define NN 50000            // nodes
#define NE 800000           // edges
#define NG 512              // graphs
#define DD 128              // node hidden
#define MM 256              // message hidden
#define TT 4                // edge types
#define NPASS 4
#define GH 256              // graph hidden

// ---------------- scratch (static __device__, no allocations) ----------------
__device__ float g_h[NN * DD];                // node hidden state
__device__ float g_preagg[NN * (TT * DD)];    // (N, 512) node-major [t0|t1|t2|t3]
__device__ int   g_counts[NN * TT];
__device__ float g_msgs[NN * MM];
__device__ float g_gi[NN * 3 * DD];
__device__ float g_gh[NN * 3 * DD];
__device__ float g_attn[NN];
__device__ int   g_hist[NN];
__device__ int   g_cursor[NN];
__device__ int   g_off[NN + 1];
__device__ int2  g_csr[NE];                   // (dst, type) sorted by src

// ---------------- setup kernels ----------------
__global__ void k_zero2(int* a, int* b, int n) {
    int i = blockIdx.x * blockDim.x + threadIdx.x;
    if (i < n) { a[i] = 0; b[i] = 0; }
}

__global__ void k_hist(const int* __restrict__ src, int* __restrict__ hist) {
    int i = blockIdx.x * blockDim.x + threadIdx.x;
    if (i < NE) atomicAdd(&hist[src[i]], 1);
}

// single-block chunked exclusive scan of g_hist -> g_off
__global__ void k_scan(const int* __restrict__ hist, int* __restrict__ off) {
    __shared__ int sh[1024];
    __shared__ int s_run;
    int tid = threadIdx.x;
    if (tid == 0) s_run = 0;
    __syncthreads();
    for (int base = 0; base < NN; base += 1024) {
        int i = base + tid;
        int v = (i < NN) ? hist[i] : 0;
        sh[tid] = v;
        __syncthreads();
        for (int o = 1; o < 1024; o <<= 1) {
            int t = (tid >= o) ? sh[tid - o] : 0;
            __syncthreads();
            sh[tid] += t;
            __syncthreads();
        }
        int run = s_run;
        if (i < NN) off[i] = run + sh[tid] - v;
        __syncthreads();
        if (tid == 1023) s_run = run + sh[1023];
        __syncthreads();
    }
    if (tid == 0) off[NN] = NE;
}

__global__ void k_scatter(const int* __restrict__ src, const int* __restrict__ dst,
                          const int* __restrict__ typ,
                          const int* __restrict__ off, int* __restrict__ cursor,
                          int2* __restrict__ csr) {
    int i = blockIdx.x * blockDim.x + threadIdx.x;
    if (i >= NE) return;
    int s = src[i];
    int pos = off[s] + atomicAdd(&cursor[s], 1);
    csr[pos] = make_int2(dst[i], typ[i]);
}

__global__ void k_embed(const int* __restrict__ nt, const float* __restrict__ emb,
                        float* __restrict__ h) {
    int t = blockIdx.x * blockDim.x + threadIdx.x;
    if (t >= NN * 32) return;
    int node = t >> 5, c = t & 31;
    reinterpret_cast<float4*>(h)[t] =
        reinterpret_cast<const float4*>(emb)[nt[node] * 32 + c];
}

// ---------------- per-pass: CSR aggregation (warp per node) ----------------
__global__ void k_agg(const float* __restrict__ h, const int* __restrict__ off,
                      const int2* __restrict__ csr,
                      float* __restrict__ preagg, int* __restrict__ counts) {
    int warp = (blockIdx.x * blockDim.x + threadIdx.x) >> 5;
    int lane = threadIdx.x & 31;
    if (warp >= NN) return;
    int beg = off[warp], end = off[warp + 1];
    float4 a0 = make_float4(0, 0, 0, 0), a1 = a0, a2 = a0, a3 = a0;
    int c0 = 0, c1 = 0, c2 = 0, c3 = 0;
    const float4* h4 = reinterpret_cast<const float4*>(h);
    for (int e = beg; e < end; ++e) {
        int2 dt = csr[e];
        float4 v = h4[dt.x * 32 + lane];
        switch (dt.y) {
            case 0: a0.x += v.x; a0.y += v.y; a0.z += v.z; a0.w += v.w; c0++; break;
            case 1: a1.x += v.x; a1.y += v.y; a1.z += v.z; a1.w += v.w; c1++; break;
            case 2: a2.x += v.x; a2.y += v.y; a2.z += v.z; a2.w += v.w; c2++; break;
            default:a3.x += v.x; a3.y += v.y; a3.z += v.z; a3.w += v.w; c3++; break;
        }
    }
    float4* p4 = reinterpret_cast<float4*>(preagg);
    int base = warp * 128;  // 512 floats = 128 float4 per node
    p4[base +       lane] = a0;
    p4[base +  32 + lane] = a1;
    p4[base +  64 + lane] = a2;
    p4[base +  96 + lane] = a3;
    if (lane == 0) {
        counts[warp * 4 + 0] = c0; counts[warp * 4 + 1] = c1;
        counts[warp * 4 + 2] = c2; counts[warp * 4 + 3] = c3;
    }
}

// ---------------- TF32 tensor-core GEMM 128x128x32, fused epilogues ----------------
// MODE 0: C = acc + bias[col]
// MODE 1: C = relu(acc + sum_t counts[r][t]*bmsg[t*MM+col])
// MODE 2: atomicAdd(gout[n2g[r]*GH+col], attn[r]*(acc+bias[col]))

__device__ __forceinline__ unsigned f2tf(float x) {
    unsigned r;
    asm("cvt.rna.tf32.f32 %0, %1;" : "=r"(r) : "f"(x));
    return r;
}

__device__ __forceinline__ void mma_tf32(float* c, const unsigned* a, const unsigned* b) {
    asm volatile(
        "mma.sync.aligned.m16n8k8.row.col.f32.tf32.tf32.f32 "
        "{%0,%1,%2,%3}, {%4,%5,%6,%7}, {%8,%9}, {%0,%1,%2,%3};"
        : "+f"(c[0]), "+f"(c[1]), "+f"(c[2]), "+f"(c[3])
        : "r"(a[0]), "r"(a[1]), "r"(a[2]), "r"(a[3]), "r"(b[0]), "r"(b[1]));
}

template <int MODE, bool TRANSB>
__global__ void __launch_bounds__(256)
k_mma(const float* __restrict__ A, const float* __restrict__ B,
      float* __restrict__ C, int Nrows, int K, int Ncols,
      const float* __restrict__ bias,
      const int* __restrict__ counts, const float* __restrict__ bmsg,
      const float* __restrict__ attn, const int* __restrict__ n2g,
      float* __restrict__ gout) {
    constexpr int BM = 128, BN = 128, BK = 32;
    constexpr int SA = 36, SB = 136;            // conflict-free strides
    __shared__ unsigned As[BM][SA];             // [m][k]
    __shared__ unsigned Bs[BK][SB];             // [k][n]

    const int tid = threadIdx.x;
    const int lane = tid & 31;
    const int warp = tid >> 5;
    const int rowBase = blockIdx.x * BM;
    const int colBase = blockIdx.y * BN;
    const int wm = (warp & 3) * 32;             // warp M offset
    const int wn = (warp >> 2) * 64;            // warp N offset
    const int qrow = lane >> 2;                 // 0..7
    const int qcol = lane & 3;                  // 0..3

    float acc[2][8][4];
#pragma unroll
    for (int mt = 0; mt < 2; mt++)
#pragma unroll
        for (int nt = 0; nt < 8; nt++)
#pragma unroll
            for (int q = 0; q < 4; q++) acc[mt][nt][q] = 0.f;

    // staging registers for the software pipeline
    float4 aR[4];
    float4 bR[4];
    const int aRow0 = tid >> 3;                 // 0..31 (stride 32, 4 iters)
    const int aCol = (tid & 7) * 4;             // 0..28
    const int bnRow = tid >> 3;                 // non-trans: k = tid/8
    const int btN = tid >> 1;                   // trans: n = tid/2
    const int btK = (tid & 1) * 16;             // trans: k segment

    auto loadA = [&](int k0) {
#pragma unroll
        for (int i = 0; i < 4; i++) {
            int row = aRow0 + 32 * i;
            if (rowBase + row < Nrows)
                aR[i] = *reinterpret_cast<const float4*>(
                    A + (size_t)(rowBase + row) * K + k0 + aCol);
            else
                aR[i] = make_float4(0, 0, 0, 0);
        }
    };
    auto loadB = [&](int k0) {
        if (!TRANSB) {
#pragma unroll
            for (int i = 0; i < 4; i++) {
                int n = ((tid & 7) + 8 * i) * 4;
                bR[i] = *reinterpret_cast<const float4*>(
                    B + (size_t)(k0 + bnRow) * Ncols + colBase + n);
            }
        } else {
#pragma unroll
            for (int i = 0; i < 4; i++) {
                int k4 = btK + 4 * i;
                bR[i] = *reinterpret_cast<const float4*>(
                    B + (size_t)(colBase + btN) * K + k0 + k4);
            }
        }
    };
    auto storeS = [&]() {
#pragma unroll
        for (int i = 0; i < 4; i++) {
            int row = aRow0 + 32 * i;
            As[row][aCol + 0] = f2tf(aR[i].x);
            As[row][aCol + 1] = f2tf(aR[i].y);
            As[row][aCol + 2] = f2tf(aR[i].z);
            As[row][aCol + 3] = f2tf(aR[i].w);
        }
        if (!TRANSB) {
#pragma unroll
            for (int i = 0; i < 4; i++) {
                int n = ((tid & 7) + 8 * i) * 4;
                Bs[bnRow][n + 0] = f2tf(bR[i].x);
                Bs[bnRow][n + 1] = f2tf(bR[i].y);
                Bs[bnRow][n + 2] = f2tf(bR[i].z);
                Bs[bnRow][n + 3] = f2tf(bR[i].w);
            }
        } else {
#pragma unroll
            for (int i = 0; i < 4; i++) {
                int k4 = btK + 4 * i;
                Bs[k4 + 0][btN] = f2tf(bR[i].x);
                Bs[k4 + 1][btN] = f2tf(bR[i].y);
                Bs[k4 + 2][btN] = f2tf(bR[i].z);
                Bs[k4 + 3][btN] = f2tf(bR[i].w);
            }
        }
    };

    loadA(0);
    loadB(0);
    for (int k0 = 0; k0 < K; k0 += BK) {
        storeS();
        __syncthreads();
        if (k0 + BK < K) { loadA(k0 + BK); loadB(k0 + BK); }
#pragma unroll
        for (int kk = 0; kk < BK / 8; kk++) {
            unsigned af[2][4];
#pragma unroll
            for (int mt = 0; mt < 2; mt++) {
                af[mt][0] = As[wm + mt * 16 + qrow][kk * 8 + qcol];
                af[mt][1] = As[wm + mt * 16 + qrow + 8][kk * 8 + qcol];
                af[mt][2] = As[wm + mt * 16 + qrow][kk * 8 + qcol + 4];
                af[mt][3] = As[wm + mt * 16 + qrow + 8][kk * 8 + qcol + 4];
            }
            unsigned bf[8][2];
#pragma unroll
            for (int nt = 0; nt < 8; nt++) {
                bf[nt][0] = Bs[kk * 8 + qcol][wn + nt * 8 + qrow];
                bf[nt][1] = Bs[kk * 8 + qcol + 4][wn + nt * 8 + qrow];
            }
#pragma unroll
            for (int mt = 0; mt < 2; mt++)
#pragma unroll
                for (int nt = 0; nt < 8; nt++)
                    mma_tf32(acc[mt][nt], af[mt], bf[nt]);
        }
        __syncthreads();
    }

    // epilogue: per mma-tile fragment layout
    // c0: (qrow, 2*qcol) c1: (qrow, 2*qcol+1) c2/c3: (qrow+8, same)
#pragma unroll
    for (int mt = 0; mt < 2; mt++) {
#pragma unroll
        for (int half = 0; half < 2; half++) {
            int r = rowBase + wm + mt * 16 + qrow + half * 8;
            if (r >= Nrows) continue;
            float ct0 = 0, ct1 = 0, ct2 = 0, ct3 = 0, at = 0;
            int gidx = 0;
            if (MODE == 1) {
                ct0 = (float)counts[r * 4 + 0]; ct1 = (float)counts[r * 4 + 1];
                ct2 = (float)counts[r * 4 + 2]; ct3 = (float)counts[r * 4 + 3];
            } else if (MODE == 2) {
                at = attn[r];
                gidx = n2g[r];
            }
#pragma unroll
            for (int nt = 0; nt < 8; nt++) {
#pragma unroll
                for (int e = 0; e < 2; e++) {
                    int c = colBase + wn + nt * 8 + 2 * qcol + e;
                    float v = acc[mt][nt][half * 2 + e];
                    if (MODE == 1) {
                        v += ct0 * bmsg[c] + ct1 * bmsg[MM + c] +
                             ct2 * bmsg[2 * MM + c] + ct3 * bmsg[3 * MM + c];
                        C[(size_t)r * Ncols + c] = fmaxf(v, 0.f);
                    } else if (MODE == 0) {
                        C[(size_t)r * Ncols + c] = v + bias[c];
                    } else {
                        atomicAdd(&gout[(size_t)gidx * GH + c], at * (v + bias[c]));
                    }
                }
            }
        }
    }
}

// ---------------- GRU gates (elementwise) ----------------
__global__ void k_gates(const float* __restrict__ gi, const float* __restrict__ gh,
                        float* __restrict__ h) {
    int i = blockIdx.x * blockDim.x + threadIdx.x;
    if (i >= NN * DD) return;
    int n = i >> 7, j = i & 127;
    const float* gin = gi + (size_t)n * 3 * DD;
    const float* ghn = gh + (size_t)n * 3 * DD;
    float r = 1.f / (1.f + expf(-(gin[j] + ghn[j])));
    float z = 1.f / (1.f + expf(-(gin[DD + j] + ghn[DD + j])));
    float nn = tanhf(gin[2 * DD + j] + r * ghn[2 * DD + j]);
    h[i] = (1.f - z) * nn + z * h[i];
}

// ---------------- readout attn (warp per node) ----------------
__global__ void k_attn(const float* __restrict__ h, const float* __restrict__ wg,
                       const float* __restrict__ bg, float* __restrict__ attn) {
    int warp = (blockIdx.x * blockDim.x + threadIdx.x) >> 5;
    int lane = threadIdx.x & 31;
    if (warp >= NN) return;
    const float4* h4 = reinterpret_cast<const float4*>(h + (size_t)warp * DD);
    const float4* w4 = reinterpret_cast<const float4*>(wg);
    float4 a = h4[lane], b = w4[lane];
    float s = a.x * b.x + a.y * b.y + a.z * b.z + a.w * b.w;
#pragma unroll
    for (int o = 16; o; o >>= 1) s += __shfl_xor_sync(0xFFFFFFFFu, s, o);
    if (lane == 0) attn[warp] = 1.f / (1.f + expf(-(s + bg[0])));
}

// ---------------- launch ----------------
static inline void* symaddr(const void* sym) {
    void* p = nullptr;
    cudaGetSymbolAddress(&p, sym);
    return p;
}

extern "C" void kernel_launch(void* const* d_in, const int* in_sizes, int n_in,
                              void* d_out, int out_size) {
    const int*   node_types = (const int*)d_in[0];
    const int*   edge_src   = (const int*)d_in[1];
    const int*   edge_dst   = (const int*)d_in[2];
    const int*   edge_type  = (const int*)d_in[3];
    const int*   node2graph = (const int*)d_in[4];
    const float* emb   = (const float*)d_in[5];
    const float* W_msg = (const float*)d_in[6];   // (T,D,M) = (512,256) concat
    const float* b_msg = (const float*)d_in[7];   // (T,M)
    const float* W_ih  = (const float*)d_in[8];   // (384,256)
    const float* W_hh  = (const float*)d_in[9];   // (384,128)
    const float* b_ih  = (const float*)d_in[10];
    const float* b_hh  = (const float*)d_in[11];
    const float* w_gate= (const float*)d_in[12];  // (128)
    const float* b_gate= (const float*)d_in[13];  // (1)
    const float* W_g   = (const float*)d_in[14];  // (128,256)
    const float* b_g   = (const float*)d_in[15];  // (256)
    float* out = (float*)d_out;

    float* h      = (float*)symaddr(g_h);
    float* preagg = (float*)symaddr(g_preagg);
    int*   counts = (int*)  symaddr(g_counts);
    float* msgs   = (float*)symaddr(g_msgs);
    float* gi     = (float*)symaddr(g_gi);
    float* gh     = (float*)symaddr(g_gh);
    float* attn   = (float*)symaddr(g_attn);
    int*   hist   = (int*)  symaddr(g_hist);
    int*   cursor = (int*)  symaddr(g_cursor);
    int*   off    = (int*)  symaddr(g_off);
    int2*  csr    = (int2*) symaddr(g_csr);

    // --- build CSR by src ---
    k_zero2<<<(NN + 255) / 256, 256>>>(hist, cursor, NN);
    k_hist<<<(NE + 255) / 256, 256>>>(edge_src, hist);
    k_scan<<<1, 1024>>>(hist, off);
    k_scatter<<<(NE + 255) / 256, 256>>>(edge_src, edge_dst, edge_type, off, cursor, csr);

    // --- init h = emb_table[node_types] ---
    k_embed<<<(NN * 32 + 255) / 256, 256>>>(node_types, emb, h);

    const int rowBlocks = (NN + 127) / 128;  // 391

    for (int p = 0; p < NPASS; p++) {
        k_agg<<<(NN * 32 + 255) / 256, 256>>>(h, off, csr, preagg, counts);
        {   // msgs = relu(pre_agg @ W_msg_cat + counts . b_msg)
            dim3 g(rowBlocks, MM / 128);
            k_mma<1, false><<<g, 256>>>(preagg, W_msg, msgs, NN, TT * DD, MM,
                                        nullptr, counts, b_msg, nullptr, nullptr, nullptr);
        }
        {   // gi = msgs @ W_ih^T + b_ih
            dim3 g(rowBlocks, (3 * DD) / 128);
            k_mma<0, true><<<g, 256>>>(msgs, W_ih, gi, NN, MM, 3 * DD,
                                       b_ih, nullptr, nullptr, nullptr, nullptr, nullptr);
        }
        {   // gh = h @ W_hh^T + b_hh
            dim3 g(rowBlocks, (3 * DD) / 128);
            k_mma<0, true><<<g, 256>>>(h, W_hh, gh, NN, DD, 3 * DD,
                                       b_hh, nullptr, nullptr, nullptr, nullptr, nullptr);
        }
        k_gates<<<(NN * DD + 255) / 256, 256>>>(gi, gh, h);
    }

    // --- output: h first, then gated graph readout ---
    cudaMemcpyAsync(out, h, (size_t)NN * DD * sizeof(float),
                    cudaMemcpyDeviceToDevice);
    float* gout = out + ((size_t)out_size - (size_t)NG * GH);
    cudaMemsetAsync(gout, 0, (size_t)NG * GH * sizeof(float));

    k_attn<<<(NN * 32 + 255) / 256, 256>>>(h, w_gate, b_gate, attn);
    {
        dim3 g(rowBlocks, GH / 128);
        k_mma<2, false><<<g, 256>>>(h, W_g, nullptr, NN, DD, GH,
                                    b_g, nullptr, nullptr, attn, node2graph, gout);
    }
}